// round 11
// baseline (speedup 1.0000x reference)
#include <cuda_runtime.h>
#include <cuda_bf16.h>
#include <stdint.h>

// ---------------- static scratch ----------------
#define KS   (1 << 19)     // key space: 16 batches * 32^3 voxels
#define NMAX (1 << 19)
#define DD   64
#define BSTRIDE 128        // fixed per-bucket capacity (mean fill ~11.6)
#define NEG_INF __int_as_float(0xFF800000)
typedef unsigned long long ull;

#define M24 0xFFFFFFull
#define VMASK ((1ull << 48) - 1ull)

__device__ __align__(16) int g_pcount[KS];
__device__ __align__(16) int g_poff[KS];
__device__ __align__(16) int g_rank[KS];
__device__ int      g_ukeys[KS];
__device__ int      g_pkey[NMAX];
__device__ int      g_pinv[NMAX];
__device__ int      g_order[NMAX];
__device__ int      g_pcursor[KS];
__device__ __align__(16) int g_ucount[KS];
__device__ __align__(16) int g_ucnt2[KS];
__device__ __align__(16) int g_uoff2[KS];
__device__ int      g_vbuf2[(size_t)KS * BSTRIDE];   // 268MB fixed-stride buckets
__device__ ull      g_st0[128];
__device__ ull      g_st1[128];
__device__ int      g_M;
__device__ int      g_Eu;

// ---------------- kernels ----------------

// histogram keys; fixed strides (pos in [0,128) => q in [0,31]) match ref order
__global__ void k_key(const float* __restrict__ pos, const int* __restrict__ batch, int N) {
    int i = blockIdx.x * blockDim.x + threadIdx.x;
    if (i >= N) return;
    int q0 = (int)floorf(pos[i * 3 + 0] * 0.25f);
    int q1 = (int)floorf(pos[i * 3 + 1] * 0.25f);
    int q2 = (int)floorf(pos[i * 3 + 2] * 0.25f);
    int key = (batch[i] << 15) | (q0 << 10) | (q1 << 5) | q2;
    if (key < 0 || key >= KS) key = 0;
    g_pkey[i] = key;
    atomicAdd(&g_pcount[key], 1);
}

// dual-payload lookback scan: bits[0:24)=count prefix, [24:48)=indicator prefix, [62:64)=flag
__global__ void k_scan0() {
    const int4* __restrict__ in = (const int4*)g_pcount;
    __shared__ ull ws[32];
    __shared__ ull s_exc;
    int t = threadIdx.x, b = blockIdx.x;
    int4 a = in[b * 1024 + t];
    ull px = (ull)(unsigned)a.x + ((ull)(a.x > 0) << 24);
    ull py = (ull)(unsigned)a.y + ((ull)(a.y > 0) << 24);
    ull pz = (ull)(unsigned)a.z + ((ull)(a.z > 0) << 24);
    ull pw = (ull)(unsigned)a.w + ((ull)(a.w > 0) << 24);
    ull s = px + py + pz + pw;
    ull inc = s;
#pragma unroll
    for (int o = 1; o < 32; o <<= 1) {
        ull n = __shfl_up_sync(0xffffffffu, inc, o);
        if ((t & 31) >= o) inc += n;
    }
    if ((t & 31) == 31) ws[t >> 5] = inc;
    __syncthreads();
    if (t < 32) {
        ull wv = ws[t]; ull winc = wv;
#pragma unroll
        for (int o = 1; o < 32; o <<= 1) {
            ull n = __shfl_up_sync(0xffffffffu, winc, o);
            if (t >= o) winc += n;
        }
        ws[t] = winc - wv;
    }
    __syncthreads();
    inc += ws[t >> 5];
    if (t == 1023)
        *(volatile ull*)&g_st0[b] = inc | ((b == 0 ? 2ULL : 1ULL) << 62);
    if (t == 0) {
        ull exc = 0;
        if (b > 0) {
            int j = b - 1;
            while (true) {
                ull v;
                do { v = *(volatile ull*)&g_st0[j]; } while ((v >> 62) == 0ULL);
                exc += v & VMASK;
                if ((v >> 62) == 2ULL) break;
                j--;
            }
        }
        s_exc = exc;
    }
    __syncthreads();
    ull exc = s_exc;
    if (t == 1023) {
        if (b > 0)
            *(volatile ull*)&g_st0[b] = ((exc + inc) & VMASK) | (2ULL << 62);
        if (b == 127) g_M = (int)(((exc + inc) >> 24) & M24);
    }
    ull base = exc + inc - s;
    ull r0 = base, r1 = base + px, r2 = r1 + py, r3 = r2 + pz;
    int idx = b * 1024 + t;
    int4 off  = make_int4((int)(r0 & M24), (int)(r1 & M24), (int)(r2 & M24), (int)(r3 & M24));
    int4 rank = make_int4((int)((r0 >> 24) & M24), (int)((r1 >> 24) & M24),
                          (int)((r2 >> 24) & M24), (int)((r3 >> 24) & M24));
    ((int4*)g_poff)[idx] = off;
    ((int4*)g_rank)[idx] = rank;
    int kbase = idx * 4;
    if (a.x) g_ukeys[rank.x] = kbase;
    if (a.y) g_ukeys[rank.y] = kbase + 1;
    if (a.z) g_ukeys[rank.z] = kbase + 2;
    if (a.w) g_ukeys[rank.w] = kbase + 3;
}

// counting-sort order + pinv; also resets scan0's lookback status for the next replay
__global__ void k_porder(int N) {
    if (blockIdx.x == 0 && threadIdx.x < 128) g_st0[threadIdx.x] = 0ULL;
    int i = blockIdx.x * blockDim.x + threadIdx.x;
    if (i >= N) return;
    int key = g_pkey[i];
    int p = g_poff[key] + atomicAdd(&g_pcursor[key], 1);
    if (p >= 0 && p < NMAX) g_order[p] = i;
    g_pinv[i] = g_rank[key];
}

// fused gather: x-max (all 16 lanes/voxel) + pos-mean (lanes dq<3); self-cleans pcount/pcursor
__global__ void k_gather(const float* __restrict__ x, const float* __restrict__ pos,
                         float* __restrict__ out, long out_size) {
    int idx = blockIdx.x * blockDim.x + threadIdx.x;   // KS*16 threads
    int voxel = idx >> 4, dq = idx & 15;
    if (voxel >= g_M) return;
    int ukey = g_ukeys[voxel];
    int off = g_poff[ukey], cnt = g_pcount[ukey];
    float4 m = make_float4(NEG_INF, NEG_INF, NEG_INF, NEG_INF);
    float s = 0.f;
    for (int j = 0; j < cnt; j++) {
        int p = g_order[off + j];                      // warp-uniform per voxel -> broadcast
        float4 v = ((const float4*)x)[p * 16 + dq];
        m.x = fmaxf(m.x, v.x); m.y = fmaxf(m.y, v.y);
        m.z = fmaxf(m.z, v.z); m.w = fmaxf(m.w, v.w);
        if (dq < 3) s += pos[p * 3 + dq];
    }
    ((float4*)out)[voxel * 16 + dq] = m;
    if (dq < 3) {
        long o = (long)g_M * DD + (long)voxel * 3 + dq;
        if (o < out_size) out[o] = s / (float)cnt;
    }
    if (dq == 0) { g_pcount[ukey] = 0; g_pcursor[ukey] = 0; }   // self-clean (after all reads)
}

// 2 edges/thread: gather pinv, write v DIRECTLY into fixed-stride bucket (no scan/scatter pass)
__global__ void k_ecount(const int* __restrict__ ei, int E) {
    int e2 = blockIdx.x * blockDim.x + threadIdx.x;
    int e = e2 * 2;
    if (e >= E) return;
    int4 q = ((const int4*)ei)[e2];
    {
        int u = g_pinv[q.x], v = g_pinv[q.y];
        if (u != v) {
            int seq = atomicAdd(&g_ucount[u], 1);
            if (seq < BSTRIDE) g_vbuf2[(size_t)u * BSTRIDE + seq] = v;
        }
    }
    if (e + 1 < E) {
        int u = g_pinv[q.z], v = g_pinv[q.w];
        if (u != v) {
            int seq = atomicAdd(&g_ucount[u], 1);
            if (seq < BSTRIDE) g_vbuf2[(size_t)u * BSTRIDE + seq] = v;
        }
    }
}

// warp per bucket: bitonic-32 + ballot dedup (len<=32) or warp rank-sort (<=128);
// self-cleans ucount
__global__ void k_sortuniq() {
    int u = (blockIdx.x * blockDim.x + threadIdx.x) >> 5;
    int lane = threadIdx.x & 31;
    if (u >= g_M) return;
    int len = g_ucount[u];                             // broadcast load
    if (lane == 0) g_ucount[u] = 0;                    // self-clean (all lanes already read)
    if (len > BSTRIDE) len = BSTRIDE;
    size_t base = (size_t)u * BSTRIDE;
    if (len == 0) { if (lane == 0) g_ucnt2[u] = 0; return; }

    if (len <= 32) {
        int v = (lane < len) ? g_vbuf2[base + lane] : 0x7FFFFFFF;
#pragma unroll
        for (int k = 2; k <= 32; k <<= 1) {
#pragma unroll
            for (int j = k >> 1; j > 0; j >>= 1) {
                int other = __shfl_xor_sync(0xffffffffu, v, j);
                bool up = ((lane & k) == 0);
                bool keepMin = (((lane & j) == 0) == up);
                v = keepMin ? min(v, other) : max(v, other);
            }
        }
        int prev = __shfl_up_sync(0xffffffffu, v, 1);
        bool keep = (lane < len) && (lane == 0 || v != prev);
        unsigned mask = __ballot_sync(0xffffffffu, keep);
        if (keep) g_vbuf2[base + __popc(mask & ((1u << lane) - 1u))] = v;
        if (lane == 0) g_ucnt2[u] = __popc(mask);
    } else {
        int vals[4]; int rnk[4];
        int nPer = (len + 31) >> 5;
#pragma unroll
        for (int t = 0; t < 4; t++) { vals[t] = 0; rnk[t] = 0; }
        for (int t = 0; t < nPer; t++) {
            int i = lane + 32 * t;
            if (i < len) vals[t] = g_vbuf2[base + i];
        }
        for (int j = 0; j < len; j++) {
            int vj = g_vbuf2[base + j];                // warp-uniform -> broadcast
            for (int t = 0; t < nPer; t++) {
                int i = lane + 32 * t;
                if (i < len) rnk[t] += (vj < vals[t]) || (vj == vals[t] && j < i);
            }
        }
        __syncwarp();
        for (int t = 0; t < nPer; t++) {
            int i = lane + 32 * t;
            if (i < len) g_vbuf2[base + rnk[t]] = vals[t];
        }
        __syncwarp();
        int c = 0, lastv = -1;
        for (int b2 = 0; b2 < len; b2 += 32) {
            int i = b2 + lane;
            int v = (i < len) ? g_vbuf2[base + i] : 0;
            int prev = __shfl_up_sync(0xffffffffu, v, 1);
            if (lane == 0) prev = (b2 == 0) ? v - 1 : lastv;
            int endv = __shfl_sync(0xffffffffu, v, 31);
            bool keep = (i < len) && (v != prev);
            unsigned mask = __ballot_sync(0xffffffffu, keep);
            if (keep) g_vbuf2[base + c + __popc(mask & ((1u << lane) - 1u))] = v;
            c += __popc(mask);
            lastv = endv;
        }
        if (lane == 0) g_ucnt2[u] = c;
    }
}

// lookback scan ucnt2 -> uoff2 (+g_Eu); zeroes ucnt2 in place (self-clean)
__global__ void k_scan1() {
    const int4* __restrict__ in = (const int4*)g_ucnt2;
    int4* __restrict__ out = (int4*)g_uoff2;
    __shared__ int ws[32];
    __shared__ int s_exc;
    int t = threadIdx.x, b = blockIdx.x;
    int4 a = in[b * 1024 + t];
    ((int4*)g_ucnt2)[b * 1024 + t] = make_int4(0, 0, 0, 0);   // self-clean
    int s = a.x + a.y + a.z + a.w;
    int inc = s;
#pragma unroll
    for (int o = 1; o < 32; o <<= 1) {
        int n = __shfl_up_sync(0xffffffffu, inc, o);
        if ((t & 31) >= o) inc += n;
    }
    if ((t & 31) == 31) ws[t >> 5] = inc;
    __syncthreads();
    if (t < 32) {
        int wv = ws[t]; int winc = wv;
#pragma unroll
        for (int o = 1; o < 32; o <<= 1) {
            int n = __shfl_up_sync(0xffffffffu, winc, o);
            if (t >= o) winc += n;
        }
        ws[t] = winc - wv;
    }
    __syncthreads();
    inc += ws[t >> 5];
    if (t == 1023)
        *(volatile ull*)&g_st1[b] = ((b == 0 ? 2ULL : 1ULL) << 32) | (unsigned)inc;
    if (t == 0) {
        int exc = 0;
        if (b > 0) {
            int j = b - 1;
            while (true) {
                ull v;
                do { v = *(volatile ull*)&g_st1[j]; } while ((v >> 32) == 0ULL);
                exc += (int)(unsigned)v;
                if ((v >> 32) == 2ULL) break;
                j--;
            }
        }
        s_exc = exc;
    }
    __syncthreads();
    int exc = s_exc;
    if (t == 1023) {
        if (b > 0)
            *(volatile ull*)&g_st1[b] = (2ULL << 32) | (unsigned)(exc + inc);
        if (b == 127) g_Eu = exc + inc;
    }
    int base = exc + inc - s;
    int4 r;
    r.x = base; r.y = base + a.x; r.z = r.y + a.y; r.w = r.z + a.z;
    out[b * 1024 + t] = r;
}

// warp per voxel: edges + (fused) self-loop + new_batch; resets scan1 status
__global__ void k_write_edges(float* __restrict__ out, long out_size) {
    if (blockIdx.x == 0 && threadIdx.x < 128) g_st1[threadIdx.x] = 0ULL;
    int gw = (blockIdx.x * blockDim.x + threadIdx.x) >> 5;
    int lane = threadIdx.x & 31;
    int M = g_M, Eu = g_Eu;
    if (gw >= M) return;
    int o2 = g_uoff2[gw];
    int next = (gw + 1 < KS) ? g_uoff2[gw + 1] : Eu;
    int c = next - o2;
    size_t base = (size_t)gw * BSTRIDE;
    long ebase = (long)M * 67;
    long wbase = ebase + 2L * o2;
    for (int i = lane; i < c; i += 32) {
        int v = g_vbuf2[base + i];
        long w = wbase + 2L * i;
        if (w + 1 < out_size) { out[w] = (float)gw; out[w + 1] = (float)v; }
    }
    if (lane == 0) {
        long o1 = ebase + 2L * (Eu + gw);              // self loop
        long ob = ebase + 2L * (Eu + (long)M) + gw;    // new_batch
        if (o1 + 1 < out_size) { out[o1] = (float)gw; out[o1 + 1] = (float)gw; }
        if (ob < out_size) out[ob] = (float)(g_ukeys[gw] >> 15);
    }
}

// ---------------- streams/events (created once at program init; never during capture)
struct HxStreams {
    cudaStream_t s1;
    cudaEvent_t fork, j1;
    HxStreams() {
        cudaStreamCreateWithFlags(&s1, cudaStreamNonBlocking);
        cudaEventCreateWithFlags(&fork, cudaEventDisableTiming);
        cudaEventCreateWithFlags(&j1, cudaEventDisableTiming);
    }
};
static HxStreams g_hx;

// ---------------- launch ----------------
extern "C" void kernel_launch(void* const* d_in, const int* in_sizes, int n_in,
                              void* d_out, int out_size) {
    const float* x     = (const float*)d_in[0];
    const float* pos   = (const float*)d_in[1];
    const int*   ei    = (const int*)d_in[2];
    const int*   batch = (const int*)d_in[3];
    float*       out   = (float*)d_out;

    const int N = in_sizes[3];
    const int E = in_sizes[2] / 2;
    const long osz = (long)out_size;

    const int TB = 256;
    const int gN  = (N + TB - 1) / TB;
    const int gE2 = (E / 2 + TB - 1) / TB;
    cudaStream_t s0 = 0;

    // critical path: 7 kernels (arrays are self-cleaning; no zero pass)
    k_key<<<gN, TB, 0, s0>>>(pos, batch, N);
    k_scan0<<<128, 1024, 0, s0>>>();
    k_porder<<<gN, TB, 0, s0>>>(N);

    // fork: fused gather overlaps the edge chain
    cudaEventRecord(g_hx.fork, s0);
    cudaStreamWaitEvent(g_hx.s1, g_hx.fork, 0);
    k_gather<<<KS * 16 / TB, TB, 0, g_hx.s1>>>(x, pos, out, osz);

    k_ecount<<<gE2, TB, 0, s0>>>(ei, E);
    k_sortuniq<<<KS * 32 / TB, TB, 0, s0>>>();
    k_scan1<<<128, 1024, 0, s0>>>();
    k_write_edges<<<KS * 32 / TB, TB, 0, s0>>>(out, osz);

    // join
    cudaEventRecord(g_hx.j1, g_hx.s1);
    cudaStreamWaitEvent(s0, g_hx.j1, 0);
}

// round 12
// speedup vs baseline: 1.2360x; 1.2360x over previous
#include <cuda_runtime.h>
#include <cuda_bf16.h>
#include <stdint.h>

// ---------------- static scratch ----------------
#define KS   (1 << 19)     // key space: 16 batches * 32^3 voxels
#define NMAX (1 << 19)
#define EMAX (1 << 22)
#define DD   64
#define NEG_INF __int_as_float(0xFF800000)
typedef unsigned long long ull;

#define M24 0xFFFFFFull
#define VMASK ((1ull << 48) - 1ull)

__device__ __align__(16) int g_pcount[KS];
__device__ __align__(16) int g_poff[KS];
__device__ __align__(16) int g_rank[KS];
__device__ int      g_ukeys[KS];
__device__ int      g_pkey[NMAX];
__device__ int      g_pinv[NMAX];
__device__ int      g_order[NMAX];
__device__ int      g_pcursor[KS];
__device__ __align__(16) int g_ucount[KS];
__device__ __align__(16) int g_uoff[KS];
__device__ __align__(16) int g_ucnt2[KS];
__device__ __align__(16) int g_uoff2[KS];
__device__ int      g_vbuf[EMAX];            // compact 16MB (L2-resident)
__device__ ull      g_euv[EMAX];
__device__ ull      g_st0[128];
__device__ ull      g_st[2][128];
__device__ int      g_M;
__device__ int      g_Eu;

__device__ __forceinline__ const int* scan_in(int w)  { return w == 0 ? g_ucount : g_ucnt2; }
__device__ __forceinline__ int*       scan_out(int w) { return w == 0 ? g_uoff   : g_uoff2; }

// ---------------- kernels ----------------

// histogram keys; fixed strides (pos in [0,128) => q in [0,31]) match ref order
__global__ void k_key(const float* __restrict__ pos, const int* __restrict__ batch, int N) {
    int i = blockIdx.x * blockDim.x + threadIdx.x;
    if (i >= N) return;
    int q0 = (int)floorf(pos[i * 3 + 0] * 0.25f);
    int q1 = (int)floorf(pos[i * 3 + 1] * 0.25f);
    int q2 = (int)floorf(pos[i * 3 + 2] * 0.25f);
    int key = (batch[i] << 15) | (q0 << 10) | (q1 << 5) | q2;
    if (key < 0 || key >= KS) key = 0;
    g_pkey[i] = key;
    atomicAdd(&g_pcount[key], 1);
}

// dual-payload lookback scan: bits[0:24)=count prefix, [24:48)=indicator prefix, [62:64)=flag
__global__ void k_scan0() {
    const int4* __restrict__ in = (const int4*)g_pcount;
    __shared__ ull ws[32];
    __shared__ ull s_exc;
    int t = threadIdx.x, b = blockIdx.x;
    int4 a = in[b * 1024 + t];
    ull px = (ull)(unsigned)a.x + ((ull)(a.x > 0) << 24);
    ull py = (ull)(unsigned)a.y + ((ull)(a.y > 0) << 24);
    ull pz = (ull)(unsigned)a.z + ((ull)(a.z > 0) << 24);
    ull pw = (ull)(unsigned)a.w + ((ull)(a.w > 0) << 24);
    ull s = px + py + pz + pw;
    ull inc = s;
#pragma unroll
    for (int o = 1; o < 32; o <<= 1) {
        ull n = __shfl_up_sync(0xffffffffu, inc, o);
        if ((t & 31) >= o) inc += n;
    }
    if ((t & 31) == 31) ws[t >> 5] = inc;
    __syncthreads();
    if (t < 32) {
        ull wv = ws[t]; ull winc = wv;
#pragma unroll
        for (int o = 1; o < 32; o <<= 1) {
            ull n = __shfl_up_sync(0xffffffffu, winc, o);
            if (t >= o) winc += n;
        }
        ws[t] = winc - wv;
    }
    __syncthreads();
    inc += ws[t >> 5];
    if (t == 1023)
        *(volatile ull*)&g_st0[b] = inc | ((b == 0 ? 2ULL : 1ULL) << 62);
    if (t == 0) {
        ull exc = 0;
        if (b > 0) {
            int j = b - 1;
            while (true) {
                ull v;
                do { v = *(volatile ull*)&g_st0[j]; } while ((v >> 62) == 0ULL);
                exc += v & VMASK;
                if ((v >> 62) == 2ULL) break;
                j--;
            }
        }
        s_exc = exc;
    }
    __syncthreads();
    ull exc = s_exc;
    if (t == 1023) {
        if (b > 0)
            *(volatile ull*)&g_st0[b] = ((exc + inc) & VMASK) | (2ULL << 62);
        if (b == 127) g_M = (int)(((exc + inc) >> 24) & M24);
    }
    ull base = exc + inc - s;
    ull r0 = base, r1 = base + px, r2 = r1 + py, r3 = r2 + pz;
    int idx = b * 1024 + t;
    int4 off  = make_int4((int)(r0 & M24), (int)(r1 & M24), (int)(r2 & M24), (int)(r3 & M24));
    int4 rank = make_int4((int)((r0 >> 24) & M24), (int)((r1 >> 24) & M24),
                          (int)((r2 >> 24) & M24), (int)((r3 >> 24) & M24));
    ((int4*)g_poff)[idx] = off;
    ((int4*)g_rank)[idx] = rank;
    int kbase = idx * 4;
    if (a.x) g_ukeys[rank.x] = kbase;
    if (a.y) g_ukeys[rank.y] = kbase + 1;
    if (a.z) g_ukeys[rank.z] = kbase + 2;
    if (a.w) g_ukeys[rank.w] = kbase + 3;
}

// 32-bit lookback scan, packed (flag<<32)|value status
__global__ void k_scan(int which) {
    const int4* __restrict__ in = (const int4*)scan_in(which);
    int4* __restrict__ out = (int4*)scan_out(which);
    ull* st = g_st[which];
    __shared__ int ws[32];
    __shared__ int s_exc;
    int t = threadIdx.x, b = blockIdx.x;
    int4 a = in[b * 1024 + t];
    if (which == 1)                                  // self-clean ucnt2 in place
        ((int4*)g_ucnt2)[b * 1024 + t] = make_int4(0, 0, 0, 0);
    int s = a.x + a.y + a.z + a.w;
    int inc = s;
#pragma unroll
    for (int o = 1; o < 32; o <<= 1) {
        int n = __shfl_up_sync(0xffffffffu, inc, o);
        if ((t & 31) >= o) inc += n;
    }
    if ((t & 31) == 31) ws[t >> 5] = inc;
    __syncthreads();
    if (t < 32) {
        int wv = ws[t]; int winc = wv;
#pragma unroll
        for (int o = 1; o < 32; o <<= 1) {
            int n = __shfl_up_sync(0xffffffffu, winc, o);
            if (t >= o) winc += n;
        }
        ws[t] = winc - wv;
    }
    __syncthreads();
    inc += ws[t >> 5];
    if (t == 1023)
        *(volatile ull*)&st[b] = ((b == 0 ? 2ULL : 1ULL) << 32) | (unsigned)inc;
    if (t == 0) {
        int exc = 0;
        if (b > 0) {
            int j = b - 1;
            while (true) {
                ull v;
                do { v = *(volatile ull*)&st[j]; } while ((v >> 32) == 0ULL);
                exc += (int)(unsigned)v;
                if ((v >> 32) == 2ULL) break;
                j--;
            }
        }
        s_exc = exc;
    }
    __syncthreads();
    int exc = s_exc;
    if (t == 1023) {
        if (b > 0)
            *(volatile ull*)&st[b] = (2ULL << 32) | (unsigned)(exc + inc);
        if (b == 127 && which == 1) g_Eu = exc + inc;
    }
    int base = exc + inc - s;
    int4 r;
    r.x = base; r.y = base + a.x; r.z = r.y + a.y; r.w = r.z + a.z;
    out[b * 1024 + t] = r;
}

// counting-sort order + pinv; resets scan0's lookback status
__global__ void k_porder(int N) {
    if (blockIdx.x == 0 && threadIdx.x < 128) g_st0[threadIdx.x] = 0ULL;
    int i = blockIdx.x * blockDim.x + threadIdx.x;
    if (i >= N) return;
    int key = g_pkey[i];
    int p = g_poff[key] + atomicAdd(&g_pcursor[key], 1);
    if (p >= 0 && p < NMAX) g_order[p] = i;
    g_pinv[i] = g_rank[key];
}

// fused gather: x-max (16 lanes/voxel) + pos-mean (dq<3); self-cleans pcount/pcursor
__global__ void k_gather(const float* __restrict__ x, const float* __restrict__ pos,
                         float* __restrict__ out, long out_size) {
    int idx = blockIdx.x * blockDim.x + threadIdx.x;   // KS*16 threads (full warps)
    int voxel = idx >> 4, dq = idx & 15;
    bool act = (voxel < g_M);
    int ukey = 0, off = 0, cnt = 0;
    if (act) { ukey = g_ukeys[voxel]; off = g_poff[ukey]; cnt = g_pcount[ukey]; }
    float4 m = make_float4(NEG_INF, NEG_INF, NEG_INF, NEG_INF);
    float s = 0.f;
    for (int j = 0; j < cnt; j++) {
        int p = g_order[off + j];                      // warp-uniform per voxel
        float4 v = ((const float4*)x)[p * 16 + dq];
        m.x = fmaxf(m.x, v.x); m.y = fmaxf(m.y, v.y);
        m.z = fmaxf(m.z, v.z); m.w = fmaxf(m.w, v.w);
        if (dq < 3) s += pos[p * 3 + dq];
    }
    if (act) {
        ((float4*)out)[voxel * 16 + dq] = m;
        if (dq < 3) {
            long o = (long)g_M * DD + (long)voxel * 3 + dq;
            if (o < out_size) out[o] = s / (float)cnt;
        }
    }
    __syncwarp();                                      // all reads of pcount done
    if (act && dq == 0) { g_pcount[ukey] = 0; g_pcursor[ukey] = 0; }
}

// 2 edges/thread. atomicAdd's return IS the bucket slot: pack u[63:45]|seq[44:19]|v[18:0]
__global__ void k_ecount(const int* __restrict__ ei, int E) {
    int e2 = blockIdx.x * blockDim.x + threadIdx.x;
    int e = e2 * 2;
    if (e >= E) return;
    int4 q = ((const int4*)ei)[e2];
    {
        int u = g_pinv[q.x], v = g_pinv[q.y];
        ull seq = (u != v) ? (ull)atomicAdd(&g_ucount[u], 1) : 0ULL;
        g_euv[e] = ((ull)(unsigned)u << 45) | (seq << 19) | (unsigned)v;
    }
    if (e + 1 < E) {
        int u = g_pinv[q.z], v = g_pinv[q.w];
        ull seq = (u != v) ? (ull)atomicAdd(&g_ucount[u], 1) : 0ULL;
        g_euv[e + 1] = ((ull)(unsigned)u << 45) | (seq << 19) | (unsigned)v;
    }
}

// atomic-free scatter: slot precomputed in ecount
__global__ void k_escatter(int E) {
    int e = blockIdx.x * blockDim.x + threadIdx.x;
    if (e >= E) return;
    ull w = g_euv[e];
    int u = (int)(w >> 45);
    int v = (int)(w & 0x7FFFFULL);
    if (u != v) {
        int p = g_uoff[u] + (int)((w >> 19) & 0x3FFFFFFULL);
        if (p < EMAX) g_vbuf[p] = v;
    }
}

// warp per bucket: bitonic-32 + ballot dedup (len<=32) or warp rank-sort;
// self-cleans ucount; resets scan(0) status
__global__ void k_sortuniq() {
    if (blockIdx.x == 0 && threadIdx.x < 128) g_st[0][threadIdx.x] = 0ULL;
    int u = (blockIdx.x * blockDim.x + threadIdx.x) >> 5;
    int lane = threadIdx.x & 31;
    if (u >= g_M) return;
    int len = g_ucount[u];                             // broadcast
    int base = g_uoff[u];
    __syncwarp();                                      // all lanes read len
    if (lane == 0) g_ucount[u] = 0;                    // self-clean
    if (len == 0) { if (lane == 0) g_ucnt2[u] = 0; return; }

    if (len <= 32) {
        int v = (lane < len) ? g_vbuf[base + lane] : 0x7FFFFFFF;
#pragma unroll
        for (int k = 2; k <= 32; k <<= 1) {
#pragma unroll
            for (int j = k >> 1; j > 0; j >>= 1) {
                int other = __shfl_xor_sync(0xffffffffu, v, j);
                bool up = ((lane & k) == 0);
                bool keepMin = (((lane & j) == 0) == up);
                v = keepMin ? min(v, other) : max(v, other);
            }
        }
        int prev = __shfl_up_sync(0xffffffffu, v, 1);
        bool keep = (lane < len) && (lane == 0 || v != prev);
        unsigned mask = __ballot_sync(0xffffffffu, keep);
        if (keep) g_vbuf[base + __popc(mask & ((1u << lane) - 1u))] = v;
        if (lane == 0) g_ucnt2[u] = __popc(mask);
    } else if (len <= 256) {
        int vals[8]; int rnk[8];
        int nPer = (len + 31) >> 5;
#pragma unroll
        for (int t = 0; t < 8; t++) { vals[t] = 0; rnk[t] = 0; }
        for (int t = 0; t < nPer; t++) {
            int i = lane + 32 * t;
            if (i < len) vals[t] = g_vbuf[base + i];
        }
        for (int j = 0; j < len; j++) {
            int vj = g_vbuf[base + j];                 // warp-uniform -> broadcast
            for (int t = 0; t < nPer; t++) {
                int i = lane + 32 * t;
                if (i < len) rnk[t] += (vj < vals[t]) || (vj == vals[t] && j < i);
            }
        }
        __syncwarp();
        for (int t = 0; t < nPer; t++) {
            int i = lane + 32 * t;
            if (i < len) g_vbuf[base + rnk[t]] = vals[t];
        }
        __syncwarp();
        int c = 0, lastv = -1;
        for (int b2 = 0; b2 < len; b2 += 32) {
            int i = b2 + lane;
            int v = (i < len) ? g_vbuf[base + i] : 0;
            int prev = __shfl_up_sync(0xffffffffu, v, 1);
            if (lane == 0) prev = (b2 == 0) ? v - 1 : lastv;
            int endv = __shfl_sync(0xffffffffu, v, 31);
            bool keep = (i < len) && (v != prev);
            unsigned mask = __ballot_sync(0xffffffffu, keep);
            if (keep) g_vbuf[base + c + __popc(mask & ((1u << lane) - 1u))] = v;
            c += __popc(mask);
            lastv = endv;
        }
        if (lane == 0) g_ucnt2[u] = c;
    } else {
        if (lane == 0) {
            for (int i = 1; i < len; i++) {
                int key = g_vbuf[base + i];
                int j = i - 1;
                while (j >= 0 && g_vbuf[base + j] > key) { g_vbuf[base + j + 1] = g_vbuf[base + j]; j--; }
                g_vbuf[base + j + 1] = key;
            }
            int c = 0, prev = -1;
            for (int i = 0; i < len; i++) {
                int v = g_vbuf[base + i];
                if (v != prev) { g_vbuf[base + c] = v; c++; prev = v; }
            }
            g_ucnt2[u] = c;
        }
    }
}

// warp per voxel: edges + fused self-loop + new_batch; resets scan(1) status
__global__ void k_write_edges(float* __restrict__ out, long out_size) {
    if (blockIdx.x == 0 && threadIdx.x < 128) g_st[1][threadIdx.x] = 0ULL;
    int gw = (blockIdx.x * blockDim.x + threadIdx.x) >> 5;
    int lane = threadIdx.x & 31;
    int M = g_M, Eu = g_Eu;
    if (gw >= M) return;
    int o2 = g_uoff2[gw];
    int next = (gw + 1 < KS) ? g_uoff2[gw + 1] : Eu;   // ucnt2 beyond M is 0 => valid
    int c = next - o2;
    int base = g_uoff[gw];
    long ebase = (long)M * 67;
    long wbase = ebase + 2L * o2;
    for (int i = lane; i < c; i += 32) {
        int v = g_vbuf[base + i];
        long w = wbase + 2L * i;
        if (w + 1 < out_size) { out[w] = (float)gw; out[w + 1] = (float)v; }
    }
    if (lane == 0) {
        long o1 = ebase + 2L * (Eu + gw);              // self loop
        long ob = ebase + 2L * (Eu + (long)M) + gw;    // new_batch
        if (o1 + 1 < out_size) { out[o1] = (float)gw; out[o1 + 1] = (float)gw; }
        if (ob < out_size) out[ob] = (float)(g_ukeys[gw] >> 15);
    }
}

// ---------------- streams/events (created once at program init; never during capture)
struct HxStreams {
    cudaStream_t s1;
    cudaEvent_t fork, j1;
    HxStreams() {
        cudaStreamCreateWithFlags(&s1, cudaStreamNonBlocking);
        cudaEventCreateWithFlags(&fork, cudaEventDisableTiming);
        cudaEventCreateWithFlags(&j1, cudaEventDisableTiming);
    }
};
static HxStreams g_hx;

// ---------------- launch ----------------
extern "C" void kernel_launch(void* const* d_in, const int* in_sizes, int n_in,
                              void* d_out, int out_size) {
    const float* x     = (const float*)d_in[0];
    const float* pos   = (const float*)d_in[1];
    const int*   ei    = (const int*)d_in[2];
    const int*   batch = (const int*)d_in[3];
    float*       out   = (float*)d_out;

    const int N = in_sizes[3];
    const int E = in_sizes[2] / 2;
    const long osz = (long)out_size;

    const int TB = 256;
    const int gN  = (N + TB - 1) / TB;
    const int gE  = (E + TB - 1) / TB;
    const int gE2 = (E / 2 + TB - 1) / TB;
    cudaStream_t s0 = 0;

    // front chain (self-cleaning; no zero pass)
    k_key<<<gN, TB, 0, s0>>>(pos, batch, N);
    k_scan0<<<128, 1024, 0, s0>>>();
    k_porder<<<gN, TB, 0, s0>>>(N);

    // fork: fused gather overlaps the edge chain
    cudaEventRecord(g_hx.fork, s0);
    cudaStreamWaitEvent(g_hx.s1, g_hx.fork, 0);
    k_gather<<<KS * 16 / TB, TB, 0, g_hx.s1>>>(x, pos, out, osz);

    // edge chain (R10-proven compact layout)
    k_ecount<<<gE2, TB, 0, s0>>>(ei, E);
    k_scan<<<128, 1024, 0, s0>>>(0);
    k_escatter<<<gE, TB, 0, s0>>>(E);
    k_sortuniq<<<KS * 32 / TB, TB, 0, s0>>>();
    k_scan<<<128, 1024, 0, s0>>>(1);
    k_write_edges<<<KS * 32 / TB, TB, 0, s0>>>(out, osz);

    // join
    cudaEventRecord(g_hx.j1, g_hx.s1);
    cudaStreamWaitEvent(s0, g_hx.j1, 0);
}

// round 14
// speedup vs baseline: 1.3423x; 1.0860x over previous
#include <cuda_runtime.h>
#include <cuda_bf16.h>
#include <stdint.h>

// ---------------- static scratch ----------------
#define KS   (1 << 19)     // key space: 16 batches * 32^3 voxels
#define NMAX (1 << 19)
#define EMAX (1 << 22)
#define DD   64
#define NEG_INF __int_as_float(0xFF800000)
typedef unsigned long long ull;

#define M24 0xFFFFFFull
#define VMASK ((1ull << 48) - 1ull)

__device__ __align__(16) int g_pcount[KS];
__device__ __align__(16) int g_poff[KS];
__device__ __align__(16) int g_rank[KS];
__device__ int      g_ukeys[KS];
__device__ int      g_pkey[NMAX];
__device__ int      g_pinv[NMAX];
__device__ int      g_order[NMAX];
__device__ int      g_pcursor[KS];
__device__ __align__(16) int g_ucount[KS];
__device__ __align__(16) int g_uoff[KS];
__device__ __align__(16) int g_ucnt2[KS];
__device__ __align__(16) int g_uoff2[KS];
__device__ int      g_vbuf[EMAX];            // compact 16MB (L2-resident)
__device__ ull      g_euv[EMAX];
__device__ ull      g_st0[128];
__device__ ull      g_st[2][128];
__device__ int      g_M;
__device__ int      g_Eu;

__device__ __forceinline__ const int* scan_in(int w)  { return w == 0 ? g_ucount : g_ucnt2; }
__device__ __forceinline__ int*       scan_out(int w) { return w == 0 ? g_uoff   : g_uoff2; }

// ---------------- kernels ----------------

__global__ void k_zero() {
    int i = blockIdx.x * blockDim.x + threadIdx.x;   // KS/4 int4 slots
    int4 z = make_int4(0, 0, 0, 0);
    ((int4*)g_pcount)[i] = z; ((int4*)g_pcursor)[i] = z;
    ((int4*)g_ucount)[i] = z; ((int4*)g_ucnt2)[i] = z;
    if (i < 128) { g_st0[i] = 0ULL; g_st[0][i] = 0ULL; g_st[1][i] = 0ULL; }
}

// histogram keys; fixed strides (pos in [0,128) => q in [0,31]) match ref order
__global__ void k_key(const float* __restrict__ pos, const int* __restrict__ batch, int N) {
    int i = blockIdx.x * blockDim.x + threadIdx.x;
    if (i >= N) return;
    int q0 = (int)floorf(pos[i * 3 + 0] * 0.25f);
    int q1 = (int)floorf(pos[i * 3 + 1] * 0.25f);
    int q2 = (int)floorf(pos[i * 3 + 2] * 0.25f);
    int key = (batch[i] << 15) | (q0 << 10) | (q1 << 5) | q2;
    if (key < 0 || key >= KS) key = 0;
    g_pkey[i] = key;
    atomicAdd(&g_pcount[key], 1);
}

// dual-payload lookback scan: bits[0:24)=count prefix, [24:48)=indicator prefix, [62:64)=flag
__global__ void k_scan0() {
    const int4* __restrict__ in = (const int4*)g_pcount;
    __shared__ ull ws[32];
    __shared__ ull s_exc;
    int t = threadIdx.x, b = blockIdx.x;
    int4 a = in[b * 1024 + t];
    ull px = (ull)(unsigned)a.x + ((ull)(a.x > 0) << 24);
    ull py = (ull)(unsigned)a.y + ((ull)(a.y > 0) << 24);
    ull pz = (ull)(unsigned)a.z + ((ull)(a.z > 0) << 24);
    ull pw = (ull)(unsigned)a.w + ((ull)(a.w > 0) << 24);
    ull s = px + py + pz + pw;
    ull inc = s;
#pragma unroll
    for (int o = 1; o < 32; o <<= 1) {
        ull n = __shfl_up_sync(0xffffffffu, inc, o);
        if ((t & 31) >= o) inc += n;
    }
    if ((t & 31) == 31) ws[t >> 5] = inc;
    __syncthreads();
    if (t < 32) {
        ull wv = ws[t]; ull winc = wv;
#pragma unroll
        for (int o = 1; o < 32; o <<= 1) {
            ull n = __shfl_up_sync(0xffffffffu, winc, o);
            if (t >= o) winc += n;
        }
        ws[t] = winc - wv;
    }
    __syncthreads();
    inc += ws[t >> 5];
    if (t == 1023)
        *(volatile ull*)&g_st0[b] = inc | ((b == 0 ? 2ULL : 1ULL) << 62);
    if (t == 0) {
        ull exc = 0;
        if (b > 0) {
            int j = b - 1;
            while (true) {
                ull v;
                do { v = *(volatile ull*)&g_st0[j]; } while ((v >> 62) == 0ULL);
                exc += v & VMASK;
                if ((v >> 62) == 2ULL) break;
                j--;
            }
        }
        s_exc = exc;
    }
    __syncthreads();
    ull exc = s_exc;
    if (t == 1023) {
        if (b > 0)
            *(volatile ull*)&g_st0[b] = ((exc + inc) & VMASK) | (2ULL << 62);
        if (b == 127) g_M = (int)(((exc + inc) >> 24) & M24);
    }
    ull base = exc + inc - s;
    ull r0 = base, r1 = base + px, r2 = r1 + py, r3 = r2 + pz;
    int idx = b * 1024 + t;
    int4 off  = make_int4((int)(r0 & M24), (int)(r1 & M24), (int)(r2 & M24), (int)(r3 & M24));
    int4 rank = make_int4((int)((r0 >> 24) & M24), (int)((r1 >> 24) & M24),
                          (int)((r2 >> 24) & M24), (int)((r3 >> 24) & M24));
    ((int4*)g_poff)[idx] = off;
    ((int4*)g_rank)[idx] = rank;
    int kbase = idx * 4;
    if (a.x) g_ukeys[rank.x] = kbase;
    if (a.y) g_ukeys[rank.y] = kbase + 1;
    if (a.z) g_ukeys[rank.z] = kbase + 2;
    if (a.w) g_ukeys[rank.w] = kbase + 3;
}

// 32-bit lookback scan, packed (flag<<32)|value status
__global__ void k_scan(int which) {
    const int4* __restrict__ in = (const int4*)scan_in(which);
    int4* __restrict__ out = (int4*)scan_out(which);
    ull* st = g_st[which];
    __shared__ int ws[32];
    __shared__ int s_exc;
    int t = threadIdx.x, b = blockIdx.x;
    int4 a = in[b * 1024 + t];
    int s = a.x + a.y + a.z + a.w;
    int inc = s;
#pragma unroll
    for (int o = 1; o < 32; o <<= 1) {
        int n = __shfl_up_sync(0xffffffffu, inc, o);
        if ((t & 31) >= o) inc += n;
    }
    if ((t & 31) == 31) ws[t >> 5] = inc;
    __syncthreads();
    if (t < 32) {
        int wv = ws[t]; int winc = wv;
#pragma unroll
        for (int o = 1; o < 32; o <<= 1) {
            int n = __shfl_up_sync(0xffffffffu, winc, o);
            if (t >= o) winc += n;
        }
        ws[t] = winc - wv;
    }
    __syncthreads();
    inc += ws[t >> 5];
    if (t == 1023)
        *(volatile ull*)&st[b] = ((b == 0 ? 2ULL : 1ULL) << 32) | (unsigned)inc;
    if (t == 0) {
        int exc = 0;
        if (b > 0) {
            int j = b - 1;
            while (true) {
                ull v;
                do { v = *(volatile ull*)&st[j]; } while ((v >> 32) == 0ULL);
                exc += (int)(unsigned)v;
                if ((v >> 32) == 2ULL) break;
                j--;
            }
        }
        s_exc = exc;
    }
    __syncthreads();
    int exc = s_exc;
    if (t == 1023) {
        if (b > 0)
            *(volatile ull*)&st[b] = (2ULL << 32) | (unsigned)(exc + inc);
        if (b == 127 && which == 1) g_Eu = exc + inc;
    }
    int base = exc + inc - s;
    int4 r;
    r.x = base; r.y = base + a.x; r.z = r.y + a.y; r.w = r.z + a.z;
    out[b * 1024 + t] = r;
}

__global__ void k_porder(int N) {
    int i = blockIdx.x * blockDim.x + threadIdx.x;
    if (i >= N) return;
    int key = g_pkey[i];
    int p = g_poff[key] + atomicAdd(&g_pcursor[key], 1);
    if (p >= 0 && p < NMAX) g_order[p] = i;
    g_pinv[i] = g_rank[key];
}

// gather-max, unrolled x4 for MLP: 4 independent order loads then 4 x-row loads
__global__ void k_gather_x(const float* __restrict__ x, float* __restrict__ out) {
    int idx = blockIdx.x * blockDim.x + threadIdx.x;   // KS*16 threads
    int voxel = idx >> 4, dq = idx & 15;
    if (voxel >= g_M) return;
    int ukey = g_ukeys[voxel];
    int off = g_poff[ukey], cnt = g_pcount[ukey];
    float4 m = make_float4(NEG_INF, NEG_INF, NEG_INF, NEG_INF);
    const float4* __restrict__ X = (const float4*)x;
    int j = 0;
    for (; j + 3 < cnt; j += 4) {
        int p0 = g_order[off + j];
        int p1 = g_order[off + j + 1];
        int p2 = g_order[off + j + 2];
        int p3 = g_order[off + j + 3];
        float4 v0 = X[p0 * 16 + dq];
        float4 v1 = X[p1 * 16 + dq];
        float4 v2 = X[p2 * 16 + dq];
        float4 v3 = X[p3 * 16 + dq];
        m.x = fmaxf(m.x, fmaxf(fmaxf(v0.x, v1.x), fmaxf(v2.x, v3.x)));
        m.y = fmaxf(m.y, fmaxf(fmaxf(v0.y, v1.y), fmaxf(v2.y, v3.y)));
        m.z = fmaxf(m.z, fmaxf(fmaxf(v0.z, v1.z), fmaxf(v2.z, v3.z)));
        m.w = fmaxf(m.w, fmaxf(fmaxf(v0.w, v1.w), fmaxf(v2.w, v3.w)));
    }
    for (; j < cnt; j++) {
        int p = g_order[off + j];
        float4 v = X[p * 16 + dq];
        m.x = fmaxf(m.x, v.x); m.y = fmaxf(m.y, v.y);
        m.z = fmaxf(m.z, v.z); m.w = fmaxf(m.w, v.w);
    }
    ((float4*)out)[voxel * 16 + dq] = m;
}

__global__ void k_gather_pos(const float* __restrict__ pos, float* __restrict__ out, long out_size) {
    int voxel = blockIdx.x * blockDim.x + threadIdx.x;
    if (voxel >= g_M) return;
    int ukey = g_ukeys[voxel];
    int off = g_poff[ukey], cnt = g_pcount[ukey];
    float s0 = 0.f, s1 = 0.f, s2 = 0.f;
    for (int j = 0; j < cnt; j++) {
        int p = g_order[off + j];
        s0 += pos[p * 3 + 0]; s1 += pos[p * 3 + 1]; s2 += pos[p * 3 + 2];
    }
    float inv = 1.0f / (float)cnt;
    long o = (long)g_M * DD + (long)voxel * 3;
    if (o + 2 < out_size) { out[o] = s0 * inv; out[o + 1] = s1 * inv; out[o + 2] = s2 * inv; }
}

// 2 edges/thread. atomicAdd's return IS the bucket slot: pack u[63:45]|seq[44:19]|v[18:0]
__global__ void k_ecount(const int* __restrict__ ei, int E) {
    int e2 = blockIdx.x * blockDim.x + threadIdx.x;
    int e = e2 * 2;
    if (e >= E) return;
    int4 q = ((const int4*)ei)[e2];
    {
        int u = g_pinv[q.x], v = g_pinv[q.y];
        ull seq = (u != v) ? (ull)atomicAdd(&g_ucount[u], 1) : 0ULL;
        g_euv[e] = ((ull)(unsigned)u << 45) | (seq << 19) | (unsigned)v;
    }
    if (e + 1 < E) {
        int u = g_pinv[q.z], v = g_pinv[q.w];
        ull seq = (u != v) ? (ull)atomicAdd(&g_ucount[u], 1) : 0ULL;
        g_euv[e + 1] = ((ull)(unsigned)u << 45) | (seq << 19) | (unsigned)v;
    }
}

// atomic-free scatter: slot precomputed in ecount
__global__ void k_escatter(int E) {
    int e = blockIdx.x * blockDim.x + threadIdx.x;
    if (e >= E) return;
    ull w = g_euv[e];
    int u = (int)(w >> 45);
    int v = (int)(w & 0x7FFFFULL);
    if (u != v) {
        int p = g_uoff[u] + (int)((w >> 19) & 0x3FFFFFFULL);
        if (p < EMAX) g_vbuf[p] = v;
    }
}

// warp per bucket: tiered bitonic (len<=32) / warp rank-sort (<=256) / serial fallback
__global__ void k_sortuniq() {
    int u = (blockIdx.x * blockDim.x + threadIdx.x) >> 5;
    int lane = threadIdx.x & 31;
    if (u >= g_M) return;
    int len = g_ucount[u];                             // broadcast
    int base = g_uoff[u];
    if (len == 0) { if (lane == 0) g_ucnt2[u] = 0; return; }

    if (len <= 32) {
        int v = (lane < len) ? g_vbuf[base + lane] : 0x7FFFFFFF;
        if (len <= 8) {
#pragma unroll
            for (int k = 2; k <= 8; k <<= 1)
#pragma unroll 4
                for (int j = k >> 1; j > 0; j >>= 1) {
                    int other = __shfl_xor_sync(0xffffffffu, v, j);
                    bool keepMin = (((lane & j) == 0) == ((lane & k) == 0));
                    v = keepMin ? min(v, other) : max(v, other);
                }
        } else if (len <= 16) {
#pragma unroll
            for (int k = 2; k <= 16; k <<= 1)
#pragma unroll 4
                for (int j = k >> 1; j > 0; j >>= 1) {
                    int other = __shfl_xor_sync(0xffffffffu, v, j);
                    bool keepMin = (((lane & j) == 0) == ((lane & k) == 0));
                    v = keepMin ? min(v, other) : max(v, other);
                }
        } else {
#pragma unroll
            for (int k = 2; k <= 32; k <<= 1)
#pragma unroll 5
                for (int j = k >> 1; j > 0; j >>= 1) {
                    int other = __shfl_xor_sync(0xffffffffu, v, j);
                    bool keepMin = (((lane & j) == 0) == ((lane & k) == 0));
                    v = keepMin ? min(v, other) : max(v, other);
                }
        }
        int prev = __shfl_up_sync(0xffffffffu, v, 1);
        bool keep = (lane < len) && (lane == 0 || v != prev);
        unsigned mask = __ballot_sync(0xffffffffu, keep);
        if (keep) g_vbuf[base + __popc(mask & ((1u << lane) - 1u))] = v;
        if (lane == 0) g_ucnt2[u] = __popc(mask);
    } else if (len <= 256) {
        int vals[8]; int rnk[8];
        int nPer = (len + 31) >> 5;
#pragma unroll
        for (int t = 0; t < 8; t++) { vals[t] = 0; rnk[t] = 0; }
        for (int t = 0; t < nPer; t++) {
            int i = lane + 32 * t;
            if (i < len) vals[t] = g_vbuf[base + i];
        }
        for (int j = 0; j < len; j++) {
            int vj = g_vbuf[base + j];                 // warp-uniform -> broadcast
            for (int t = 0; t < nPer; t++) {
                int i = lane + 32 * t;
                if (i < len) rnk[t] += (vj < vals[t]) || (vj == vals[t] && j < i);
            }
        }
        __syncwarp();
        for (int t = 0; t < nPer; t++) {
            int i = lane + 32 * t;
            if (i < len) g_vbuf[base + rnk[t]] = vals[t];
        }
        __syncwarp();
        int c = 0, lastv = -1;
        for (int b2 = 0; b2 < len; b2 += 32) {
            int i = b2 + lane;
            int v = (i < len) ? g_vbuf[base + i] : 0;
            int prev = __shfl_up_sync(0xffffffffu, v, 1);
            if (lane == 0) prev = (b2 == 0) ? v - 1 : lastv;
            int endv = __shfl_sync(0xffffffffu, v, 31);
            bool keep = (i < len) && (v != prev);
            unsigned mask = __ballot_sync(0xffffffffu, keep);
            if (keep) g_vbuf[base + c + __popc(mask & ((1u << lane) - 1u))] = v;
            c += __popc(mask);
            lastv = endv;
        }
        if (lane == 0) g_ucnt2[u] = c;
    } else {
        if (lane == 0) {
            for (int i = 1; i < len; i++) {
                int key = g_vbuf[base + i];
                int j = i - 1;
                while (j >= 0 && g_vbuf[base + j] > key) { g_vbuf[base + j + 1] = g_vbuf[base + j]; j--; }
                g_vbuf[base + j + 1] = key;
            }
            int c = 0, prev = -1;
            for (int i = 0; i < len; i++) {
                int v = g_vbuf[base + i];
                if (v != prev) { g_vbuf[base + c] = v; c++; prev = v; }
            }
            g_ucnt2[u] = c;
        }
    }
}

// warp per voxel: lanes stride over dedup'd v's
__global__ void k_write_edges(float* __restrict__ out, long out_size) {
    int gw = (blockIdx.x * blockDim.x + threadIdx.x) >> 5;
    int lane = threadIdx.x & 31;
    if (gw >= g_M) return;
    int c = g_ucnt2[gw];
    int base = g_uoff[gw];
    long wbase = (long)g_M * 67 + 2L * g_uoff2[gw];
    for (int i = lane; i < c; i += 32) {
        int v = g_vbuf[base + i];
        long w = wbase + 2L * i;
        if (w + 1 < out_size) { out[w] = (float)gw; out[w + 1] = (float)v; }
    }
}

__global__ void k_write_tail(float* __restrict__ out, long out_size) {
    int voxel = blockIdx.x * blockDim.x + threadIdx.x;
    int M = g_M, Eu = g_Eu;
    if (voxel >= M) return;
    long ebase = (long)M * 67;
    long o1 = ebase + 2L * (Eu + voxel);
    long o2 = ebase + 2L * (Eu + (long)M) + voxel;
    if (o1 + 1 < out_size) { out[o1] = (float)voxel; out[o1 + 1] = (float)voxel; }
    if (o2 < out_size) out[o2] = (float)(g_ukeys[voxel] >> 15);
}

// ---------------- streams/events (created once at program init; never during capture)
struct HxStreams {
    cudaStream_t s1, s2;
    cudaEvent_t fork, j1, j2;
    HxStreams() {
        cudaStreamCreateWithFlags(&s1, cudaStreamNonBlocking);
        cudaStreamCreateWithFlags(&s2, cudaStreamNonBlocking);
        cudaEventCreateWithFlags(&fork, cudaEventDisableTiming);
        cudaEventCreateWithFlags(&j1, cudaEventDisableTiming);
        cudaEventCreateWithFlags(&j2, cudaEventDisableTiming);
    }
};
static HxStreams g_hx;

// ---------------- launch ----------------
extern "C" void kernel_launch(void* const* d_in, const int* in_sizes, int n_in,
                              void* d_out, int out_size) {
    const float* x     = (const float*)d_in[0];
    const float* pos   = (const float*)d_in[1];
    const int*   ei    = (const int*)d_in[2];
    const int*   batch = (const int*)d_in[3];
    float*       out   = (float*)d_out;

    const int N = in_sizes[3];
    const int E = in_sizes[2] / 2;
    const long osz = (long)out_size;

    const int TB = 256;
    const int gN  = (N + TB - 1) / TB;
    const int gE  = (E + TB - 1) / TB;
    const int gE2 = (E / 2 + TB - 1) / TB;
    cudaStream_t s0 = 0;

    // front chain
    k_zero<<<KS / 4 / TB, TB, 0, s0>>>();
    k_key<<<gN, TB, 0, s0>>>(pos, batch, N);
    k_scan0<<<128, 1024, 0, s0>>>();
    k_porder<<<gN, TB, 0, s0>>>(N);

    // fork: gathers overlap the edge chain
    cudaEventRecord(g_hx.fork, s0);
    cudaStreamWaitEvent(g_hx.s1, g_hx.fork, 0);
    cudaStreamWaitEvent(g_hx.s2, g_hx.fork, 0);
    k_gather_x<<<KS * 16 / TB, TB, 0, g_hx.s1>>>(x, out);
    k_gather_pos<<<KS / TB, TB, 0, g_hx.s2>>>(pos, out, osz);

    // edge chain (compact layout, proven)
    k_ecount<<<gE2, TB, 0, s0>>>(ei, E);
    k_scan<<<128, 1024, 0, s0>>>(0);
    k_escatter<<<gE, TB, 0, s0>>>(E);
    k_sortuniq<<<KS * 32 / TB, TB, 0, s0>>>();
    k_scan<<<128, 1024, 0, s0>>>(1);
    k_write_edges<<<KS * 32 / TB, TB, 0, s0>>>(out, osz);
    k_write_tail<<<KS / TB, TB, 0, s0>>>(out, osz);

    // join
    cudaEventRecord(g_hx.j1, g_hx.s1);
    cudaEventRecord(g_hx.j2, g_hx.s2);
    cudaStreamWaitEvent(s0, g_hx.j1, 0);
    cudaStreamWaitEvent(s0, g_hx.j2, 0);
}